// round 16
// baseline (speedup 1.0000x reference)
#include <cuda_runtime.h>
#include <cuda_bf16.h>
#include <math.h>
#include <stdint.h>

#define B_ 4
#define T_ 256
#define D_ 1024
#define H_ 16
#define HD_ 64
#define F_ 4096
#define L_ 6
#define V_ 32000
#define NPB (V_/256)          // logits partial blocks = 125

typedef long long ll;

#define BTD (B_*T_*D_)
#define BTF (B_*T_*F_)
#define MT  (B_*T_)

#define WQPAIRS (L_*(D_/2)*D_)
#define W1PAIRS (L_*(D_/2)*F_)
#define W2PAIRS (L_*(F_/2)*D_)
#define LMPAIRS ((D_/2)*V_)
#define TOTPAIRS (4ll*WQPAIRS + 2ll*W1PAIRS + (ll)W2PAIRS + (ll)LMPAIRS)

#define HPN  ((D_/2)*MT)
#define F1PN ((F_/2)*MT)

// ---------------- scratch (static device memory, no allocs) ----------------
__device__ float g_x  [BTD];
__device__ float g_qkv[3*BTD];
__device__ float g_f13[BTF];         // f1 only (w3 epilogue consumes it)
__device__ float g_cos[T_*(HD_/2)];
__device__ float g_sin[T_*(HD_/2)];
__device__ float g_pM[NPB*B_];
__device__ float g_pS[NPB*B_];

// packed activations  [kp][MT]
__device__ uint32_t g_hpH [HPN],  g_hpL [HPN];
__device__ uint32_t g_aopH[HPN],  g_aopL[HPN];
__device__ uint32_t g_f1pH[F1PN], g_f1pL[F1PN];
__device__ uint32_t g_exH [HPN],  g_exL [HPN];
// packed weights  [L*K/2][N]
__device__ uint32_t g_wqH[WQPAIRS], g_wqL[WQPAIRS];
__device__ uint32_t g_wkH[WQPAIRS], g_wkL[WQPAIRS];
__device__ uint32_t g_wvH[WQPAIRS], g_wvL[WQPAIRS];
__device__ uint32_t g_woH[WQPAIRS], g_woL[WQPAIRS];
__device__ uint32_t g_w1H[W1PAIRS], g_w1L[W1PAIRS];
__device__ uint32_t g_w3H[W1PAIRS], g_w3L[W1PAIRS];
__device__ uint32_t g_w2H[W2PAIRS], g_w2L[W2PAIRS];
__device__ uint32_t g_lmH[LMPAIRS], g_lmL[LMPAIRS];

// ---------------- control flags ----------------
__device__ int d_do_skip;
__device__ int d_exited[B_];
__device__ int d_newly[B_];
__device__ int d_exl[B_];

// ---------------------------------------------------------------------------
__device__ __forceinline__ void split_pack(float x0, float x1,
                                           uint32_t& hi, uint32_t& lo) {
    __nv_bfloat16 h0 = __float2bfloat16(x0);
    __nv_bfloat16 h1 = __float2bfloat16(x1);
    __nv_bfloat16 l0 = __float2bfloat16(x0 - __bfloat162float(h0));
    __nv_bfloat16 l1 = __float2bfloat16(x1 - __bfloat162float(h1));
    hi = ((uint32_t)__bfloat16_as_ushort(h1) << 16) | __bfloat16_as_ushort(h0);
    lo = ((uint32_t)__bfloat16_as_ushort(l1) << 16) | __bfloat16_as_ushort(l0);
}

__global__ void init_k() {
    int t = threadIdx.x;
    if (t < B_) { d_exited[t] = 0; d_newly[t] = 0; d_exl[t] = -1; }
    if (t == 0) d_do_skip = 0;
}

__global__ void finalize_k() {
    int t = threadIdx.x;
    if (t < B_) {
        int nv = d_exited[t] ? 0 : 1;
        d_newly[t] = nv;
        if (nv) d_exl[t] = L_ - 1;
    }
    if (t == 0) d_do_skip = 0;
}

__global__ void write_exl_k(float* out) {
    int t = threadIdx.x;
    if (t < B_) out[t] = (float)d_exl[t];
}

__global__ void rope_tables_k() {
    int idx = blockIdx.x * 256 + threadIdx.x;
    int t = idx >> 5;
    int i = idx & 31;
    float inv = expf(-logf(10000.f) * (2.f * (float)i) / (float)HD_);
    float f = (float)t * inv;
    g_cos[idx] = cosf(f);
    g_sin[idx] = sinf(f);
}

__global__ void embed_k(const int* __restrict__ ids, const float* __restrict__ emb) {
    ll idx = (ll)blockIdx.x * 256 + threadIdx.x;
    int tok = ids[idx >> 10];
    g_x[idx] = emb[(ll)tok * D_ + (idx & 1023)];
}

// ---- weight prepack ----
__global__ void prepack_k(const float* __restrict__ wq, const float* __restrict__ wk,
                          const float* __restrict__ wv, const float* __restrict__ wo,
                          const float* __restrict__ w1, const float* __restrict__ w2,
                          const float* __restrict__ w3, const float* __restrict__ lm) {
    ll gid = (ll)blockIdx.x * 256 + threadIdx.x;
    if (gid >= TOTPAIRS) return;
    const float* src; uint32_t *dH, *dL; ll idx; int cols;
    ll c4 = 4ll * WQPAIRS;
    if (gid < (ll)WQPAIRS)        { src = wq; dH = g_wqH; dL = g_wqL; idx = gid; cols = D_; }
    else if (gid < 2ll*WQPAIRS)   { src = wk; dH = g_wkH; dL = g_wkL; idx = gid - WQPAIRS; cols = D_; }
    else if (gid < 3ll*WQPAIRS)   { src = wv; dH = g_wvH; dL = g_wvL; idx = gid - 2ll*WQPAIRS; cols = D_; }
    else if (gid < c4)            { src = wo; dH = g_woH; dL = g_woL; idx = gid - 3ll*WQPAIRS; cols = D_; }
    else if (gid < c4 + W1PAIRS)  { src = w1; dH = g_w1H; dL = g_w1L; idx = gid - c4; cols = F_; }
    else if (gid < c4 + 2ll*W1PAIRS) { src = w3; dH = g_w3H; dL = g_w3L; idx = gid - c4 - W1PAIRS; cols = F_; }
    else if (gid < c4 + 2ll*W1PAIRS + W2PAIRS)
                                  { src = w2; dH = g_w2H; dL = g_w2L; idx = gid - c4 - 2ll*W1PAIRS; cols = D_; }
    else                          { src = lm; dH = g_lmH; dL = g_lmL; idx = gid - c4 - 2ll*W1PAIRS - W2PAIRS; cols = V_; }
    ll kp = idx / cols;
    int col = (int)(idx - kp * cols);
    float a = src[(2*kp)     * (ll)cols + col];
    float b = src[(2*kp + 1) * (ll)cols + col];
    uint32_t h, l;
    split_pack(a, b, h, l);
    dH[idx] = h; dL[idx] = l;
}

// rmsnorm; packOut: 0 none, 1 -> g_hp, 3 -> g_ex
__global__ void rmsnorm_k(const float* __restrict__ in, const float* __restrict__ w,
                          float* outF, ll inStride, ll outStride,
                          int gateMode, int rowsPerBatch, int packOut) {
    if (gateMode == 1 && d_do_skip) return;
    int row = blockIdx.x;
    if (gateMode == 2 && !d_newly[row / rowsPerBatch]) return;
    const float* xr = in + (ll)row * inStride;
    int tid = threadIdx.x;
    float4 v = reinterpret_cast<const float4*>(xr)[tid];
    float s = v.x * v.x + v.y * v.y + v.z * v.z + v.w * v.w;
    __shared__ float red[256];
    red[tid] = s; __syncthreads();
    for (int o = 128; o > 0; o >>= 1) { if (tid < o) red[tid] += red[tid + o]; __syncthreads(); }
    float scale = rsqrtf(red[0] * (1.f / (float)D_) + 1e-6f);
    float4 wv = reinterpret_cast<const float4*>(w)[tid];
    float4 ov;
    ov.x = v.x * wv.x * scale; ov.y = v.y * wv.y * scale;
    ov.z = v.z * wv.z * scale; ov.w = v.w * wv.w * scale;
    if (outF) reinterpret_cast<float4*>(outF + (ll)row * outStride)[tid] = ov;
    if (packOut) {
        uint32_t* pH = (packOut == 1) ? g_hpH : g_exH;
        uint32_t* pL = (packOut == 1) ? g_hpL : g_exL;
        uint32_t h, l;
        split_pack(ov.x, ov.y, h, l);
        pH[(ll)(2*tid)   * MT + row] = h; pL[(ll)(2*tid)   * MT + row] = l;
        split_pack(ov.z, ov.w, h, l);
        pH[(ll)(2*tid+1) * MT + row] = h; pL[(ll)(2*tid+1) * MT + row] = l;
    }
}

#define MMA_BF16(acc, a, b)                                                   \
    asm volatile(                                                             \
        "mma.sync.aligned.m16n8k16.row.col.f32.bf16.bf16.f32 "                \
        "{%0,%1,%2,%3}, {%4,%5,%6,%7}, {%8,%9}, {%0,%1,%2,%3};"               \
        : "+f"(acc[0]), "+f"(acc[1]), "+f"(acc[2]), "+f"(acc[3])              \
        : "r"(a[0]), "r"(a[1]), "r"(a[2]), "r"(a[3]), "r"(b[0]), "r"(b[1]))

// ==================== fused flash attention (RoPE inline) ==================
// grid (2, B*H); block 256 = 8 warps x 16 q-rows. K/V tiles of 64 keys.
// RoPE applied in fp32 during Q/K smem load (identical math to separate pass).
#define FLASH_SMEM ((2*32*136 + 4*32*72)*4)

__global__ __launch_bounds__(256, 1) void flash_k() {
    if (d_do_skip) return;
    extern __shared__ uint32_t fsm[];
    uint32_t* Qh = fsm;                 // [32 dp][136]
    uint32_t* Ql = Qh + 32*136;
    uint32_t* Kh = Ql + 32*136;         // [32 dp][72]
    uint32_t* Kl = Kh + 32*72;
    uint32_t* Vh = Kl + 32*72;          // [32 keypair][72]
    uint32_t* Vl = Vh + 32*72;

    const int qt = blockIdx.x;
    const int bh = blockIdx.y;
    const int b  = bh >> 4, h = bh & 15;
    const int tid = threadIdx.x;
    const int lane = tid & 31, warp = tid >> 5;
    const int lq = lane >> 2, lr = lane & 3;

    const float* qg = g_qkv;
    const float* kg = g_qkv + (ll)BTD;
    const float* vg = g_qkv + 2ll*BTD;

    // ---- load Q tile 128x64 with RoPE -> packed [dp][row] ----
    {
        int row = tid >> 1;
        int i0 = (tid & 1) * 16;
        int t = qt*128 + row;
        const float* p = qg + ((ll)(b*T_ + t))*D_ + h*HD_;
        const float* ct = g_cos + t*32;
        const float* st = g_sin + t*32;
#pragma unroll
        for (int q4 = 0; q4 < 4; q4++) {
            int i = i0 + q4*4;
            float4 x1 = *reinterpret_cast<const float4*>(p + i);
            float4 x2 = *reinterpret_cast<const float4*>(p + i + 32);
            float4 c4 = *reinterpret_cast<const float4*>(ct + i);
            float4 s4 = *reinterpret_cast<const float4*>(st + i);
            float r1x = x1.x*c4.x - x2.x*s4.x, r2x = x1.x*s4.x + x2.x*c4.x;
            float r1y = x1.y*c4.y - x2.y*s4.y, r2y = x1.y*s4.y + x2.y*c4.y;
            float r1z = x1.z*c4.z - x2.z*s4.z, r2z = x1.z*s4.z + x2.z*c4.z;
            float r1w = x1.w*c4.w - x2.w*s4.w, r2w = x1.w*s4.w + x2.w*c4.w;
            uint32_t hh, lo;
            int dp = i >> 1;
            split_pack(r1x, r1y, hh, lo); Qh[(dp    )*136 + row] = hh; Ql[(dp    )*136 + row] = lo;
            split_pack(r1z, r1w, hh, lo); Qh[(dp + 1)*136 + row] = hh; Ql[(dp + 1)*136 + row] = lo;
            split_pack(r2x, r2y, hh, lo); Qh[(16+dp    )*136 + row] = hh; Ql[(16+dp    )*136 + row] = lo;
            split_pack(r2z, r2w, hh, lo); Qh[(16+dp + 1)*136 + row] = hh; Ql[(16+dp + 1)*136 + row] = lo;
        }
    }

    float m0r = -1e30f, m1r = -1e30f, l0r = 0.f, l1r = 0.f;
    float O[8][4];
#pragma unroll
    for (int j = 0; j < 8; j++)
#pragma unroll
        for (int r = 0; r < 4; r++) O[j][r] = 0.f;

    const int qr0 = qt*128 + warp*16 + lq;
    const int qr1 = qr0 + 8;
    const int ktmax = (qt*128 + 127) >> 6;

    for (int kt = 0; kt <= ktmax; kt++) {
        // ---- load K tile with RoPE: packed along d, [dp][key] ----
        {
            int key = tid >> 2;
            int i0 = (tid & 3) * 8;
            int t = kt*64 + key;
            const float* p = kg + ((ll)(b*T_ + t))*D_ + h*HD_;
            const float* ct = g_cos + t*32;
            const float* st = g_sin + t*32;
#pragma unroll
            for (int q4 = 0; q4 < 2; q4++) {
                int i = i0 + q4*4;
                float4 x1 = *reinterpret_cast<const float4*>(p + i);
                float4 x2 = *reinterpret_cast<const float4*>(p + i + 32);
                float4 c4 = *reinterpret_cast<const float4*>(ct + i);
                float4 s4 = *reinterpret_cast<const float4*>(st + i);
                float r1x = x1.x*c4.x - x2.x*s4.x, r2x = x1.x*s4.x + x2.x*c4.x;
                float r1y = x1.y*c4.y - x2.y*s4.y, r2y = x1.y*s4.y + x2.y*c4.y;
                float r1z = x1.z*c4.z - x2.z*s4.z, r2z = x1.z*s4.z + x2.z*c4.z;
                float r1w = x1.w*c4.w - x2.w*s4.w, r2w = x1.w*s4.w + x2.w*c4.w;
                uint32_t hh, lo;
                int dp = i >> 1;
                split_pack(r1x, r1y, hh, lo); Kh[(dp    )*72 + key] = hh; Kl[(dp    )*72 + key] = lo;
                split_pack(r1z, r1w, hh, lo); Kh[(dp + 1)*72 + key] = hh; Kl[(dp + 1)*72 + key] = lo;
                split_pack(r2x, r2y, hh, lo); Kh[(16+dp    )*72 + key] = hh; Kl[(16+dp    )*72 + key] = lo;
                split_pack(r2z, r2w, hh, lo); Kh[(16+dp + 1)*72 + key] = hh; Kl[(16+dp + 1)*72 + key] = lo;
            }
        }
        // ---- load V tile: packed along key, [keypair][d] ----
        {
            int d4 = (tid & 15) * 4;
            int kpb = (tid >> 4) * 2;
#pragma unroll
            for (int kk = 0; kk < 2; kk++) {
                int kp = kpb + kk;
                const float* p0 = vg + ((ll)(b*T_ + kt*64 + 2*kp))*D_ + h*HD_ + d4;
                float4 a4 = *reinterpret_cast<const float4*>(p0);
                float4 b4 = *reinterpret_cast<const float4*>(p0 + D_);
                uint32_t hh, lo;
                split_pack(a4.x, b4.x, hh, lo); Vh[kp*72 + d4+0] = hh; Vl[kp*72 + d4+0] = lo;
                split_pack(a4.y, b4.y, hh, lo); Vh[kp*72 + d4+1] = hh; Vl[kp*72 + d4+1] = lo;
                split_pack(a4.z, b4.z, hh, lo); Vh[kp*72 + d4+2] = hh; Vl[kp*72 + d4+2] = lo;
                split_pack(a4.w, b4.w, hh, lo); Vh[kp*72 + d4+3] = hh; Vl[kp*72 + d4+3] = lo;
            }
        }
        __syncthreads();

        // ---- S = Q K^T ----
        float sa[8][4];
#pragma unroll
        for (int j = 0; j < 8; j++)
#pragma unroll
            for (int r = 0; r < 4; r++) sa[j][r] = 0.f;
        const int m0 = warp*16 + lq;
#pragma unroll
        for (int s = 0; s < 4; s++) {
            uint32_t aH[4], aL[4];
            aH[0] = Qh[(8*s + lr    )*136 + m0]; aH[1] = Qh[(8*s + lr    )*136 + m0 + 8];
            aH[2] = Qh[(8*s + lr + 4)*136 + m0]; aH[3] = Qh[(8*s + lr + 4)*136 + m0 + 8];
            aL[0] = Ql[(8*s + lr    )*136 + m0]; aL[1] = Ql[(8*s + lr    )*136 + m0 + 8];
            aL[2] = Ql[(8*s + lr + 4)*136 + m0]; aL[3] = Ql[(8*s + lr + 4)*136 + m0 + 8];
#pragma unroll
            for (int j = 0; j < 8; j++) {
                int n0 = 8*j + lq;
                uint32_t bH[2], bL[2];
                bH[0] = Kh[(8*s + lr    )*72 + n0]; bH[1] = Kh[(8*s + lr + 4)*72 + n0];
                bL[0] = Kl[(8*s + lr    )*72 + n0]; bL[1] = Kl[(8*s + lr + 4)*72 + n0];
                MMA_BF16(sa[j], aH, bL);
                MMA_BF16(sa[j], aL, bH);
                MMA_BF16(sa[j], aH, bH);
            }
        }

        // ---- scale + causal mask + online softmax ----
        float mx0 = -1e30f, mx1 = -1e30f;
#pragma unroll
        for (int j = 0; j < 8; j++) {
            int kc0 = kt*64 + 8*j + 2*lr;
            int kc1 = kc0 + 1;
            sa[j][0] = (kc0 <= qr0) ? sa[j][0]*0.125f : -1e30f;
            sa[j][1] = (kc1 <= qr0) ? sa[j][1]*0.125f : -1e30f;
            sa[j][2] = (kc0 <= qr1) ? sa[j][2]*0.125f : -1e30f;
            sa[j][3] = (kc1 <= qr1) ? sa[j][3]*0.125f : -1e30f;
            mx0 = fmaxf(mx0, fmaxf(sa[j][0], sa[j][1]));
            mx1 = fmaxf(mx1, fmaxf(sa[j][2], sa[j][3]));
        }
        mx0 = fmaxf(mx0, __shfl_xor_sync(0xffffffff, mx0, 1));
        mx0 = fmaxf(mx0, __shfl_xor_sync(0xffffffff, mx0, 2));
        mx1 = fmaxf(mx1, __shfl_xor_sync(0xffffffff, mx1, 1));
        mx1 = fmaxf(mx1, __shfl_xor_sync(0xffffffff, mx1, 2));
        float mn0 = fmaxf(m0r, mx0), mn1 = fmaxf(m1r, mx1);
        float c0 = __expf(m0r - mn0), c1 = __expf(m1r - mn1);
        float s0 = 0.f, s1 = 0.f;
#pragma unroll
        for (int j = 0; j < 8; j++) {
            sa[j][0] = __expf(sa[j][0] - mn0);
            sa[j][1] = __expf(sa[j][1] - mn0);
            sa[j][2] = __expf(sa[j][2] - mn1);
            sa[j][3] = __expf(sa[j][3] - mn1);
            s0 += sa[j][0] + sa[j][1];
            s1 += sa[j][2] + sa[j][3];
        }
        s0 += __shfl_xor_sync(0xffffffff, s0, 1);
        s0 += __shfl_xor_sync(0xffffffff, s0, 2);
        s1 += __shfl_xor_sync(0xffffffff, s1, 1);
        s1 += __shfl_xor_sync(0xffffffff, s1, 2);
        l0r = l0r * c0 + s0;
        l1r = l1r * c1 + s1;
        m0r = mn0; m1r = mn1;
#pragma unroll
        for (int j = 0; j < 8; j++) {
            O[j][0] *= c0; O[j][1] *= c0;
            O[j][2] *= c1; O[j][3] *= c1;
        }

        // ---- O += P V ----
#pragma unroll
        for (int s = 0; s < 4; s++) {
            uint32_t pH[4], pL[4];
            split_pack(sa[2*s][0],   sa[2*s][1],   pH[0], pL[0]);
            split_pack(sa[2*s][2],   sa[2*s][3],   pH[1], pL[1]);
            split_pack(sa[2*s+1][0], sa[2*s+1][1], pH[2], pL[2]);
            split_pack(sa[2*s+1][2], sa[2*s+1][3], pH[3], pL[3]);
#pragma unroll
            for (int j = 0; j < 8; j++) {
                int n0 = 8*j + lq;
                uint32_t bH[2], bL[2];
                bH[0] = Vh[(8*s + lr    )*72 + n0]; bH[1] = Vh[(8*s + lr + 4)*72 + n0];
                bL[0] = Vl[(8*s + lr    )*72 + n0]; bL[1] = Vl[(8*s + lr + 4)*72 + n0];
                MMA_BF16(O[j], pH, bL);
                MMA_BF16(O[j], pL, bH);
                MMA_BF16(O[j], pH, bH);
            }
        }
        __syncthreads();
    }

    // ---- epilogue: normalize and write ao_pack ----
    float i0 = 1.f / l0r, i1 = 1.f / l1r;
#pragma unroll
    for (int j = 0; j < 8; j++) {
        uint32_t hh, lo;
        ll o = (ll)(h*32 + 4*j + lr) * MT + b*T_ + qr0;
        split_pack(O[j][0]*i0, O[j][1]*i0, hh, lo);
        g_aopH[o] = hh; g_aopL[o] = lo;
        split_pack(O[j][2]*i1, O[j][3]*i1, hh, lo);
        g_aopH[o + 8] = hh; g_aopL[o + 8] = lo;
    }
}

// ========== fused exit-logits partials (rmsnorm of last position inline) ===
__global__ void logits_exit_k(const float* __restrict__ x,
                              const float* __restrict__ fn) {
    if (d_do_skip) return;
    int tid = threadIdx.x;
    __shared__ float hs[B_][D_];
    __shared__ float red[256];
    __shared__ float scl[B_];
    // inline rmsnorm of x[b, T-1, :]
    for (int b = 0; b < B_; b++) {
        const float* xr = x + ((ll)b * T_ + (T_ - 1)) * D_;
        float s = 0.f;
        for (int i = tid; i < D_; i += 256) {
            float v = xr[i];
            hs[b][i] = v;
            s += v * v;
        }
        red[tid] = s; __syncthreads();
        for (int o = 128; o > 0; o >>= 1) { if (tid < o) red[tid] += red[tid + o]; __syncthreads(); }
        if (tid == 0) scl[b] = rsqrtf(red[0] * (1.f / (float)D_) + 1e-6f);
        __syncthreads();
    }
    for (int i = tid; i < B_ * D_; i += 256) {
        int b = i >> 10, d = i & 1023;
        hs[b][d] = hs[b][d] * fn[d] * scl[b];
    }
    __syncthreads();

    int v = blockIdx.x * 256 + tid;
    float a[B_] = {0.f, 0.f, 0.f, 0.f};
    const uint32_t* col = g_lmH + v;
#pragma unroll 4
    for (int kp = 0; kp < D_ / 2; kp++) {
        uint32_t hv = col[(ll)kp * V_];
        float e0 = __uint_as_float(hv << 16);
        float e1 = __uint_as_float(hv & 0xffff0000u);
        a[0] = fmaf(e0, hs[0][2*kp], fmaf(e1, hs[0][2*kp+1], a[0]));
        a[1] = fmaf(e0, hs[1][2*kp], fmaf(e1, hs[1][2*kp+1], a[1]));
        a[2] = fmaf(e0, hs[2][2*kp], fmaf(e1, hs[2][2*kp+1], a[2]));
        a[3] = fmaf(e0, hs[3][2*kp], fmaf(e1, hs[3][2*kp+1], a[3]));
    }
    __shared__ float wred[8];
    __shared__ float bm;
    int lane = tid & 31, warp = tid >> 5;
    for (int b = 0; b < B_; b++) {
        float m = a[b];
#pragma unroll
        for (int o = 16; o > 0; o >>= 1) m = fmaxf(m, __shfl_xor_sync(0xffffffff, m, o));
        if (lane == 0) wred[warp] = m;
        __syncthreads();
        if (tid == 0) {
            float mm = wred[0];
            for (int i = 1; i < 8; i++) mm = fmaxf(mm, wred[i]);
            bm = mm;
        }
        __syncthreads();
        float e = __expf(a[b] - bm);
#pragma unroll
        for (int o = 16; o > 0; o >>= 1) e += __shfl_xor_sync(0xffffffff, e, o);
        __syncthreads();
        if (lane == 0) wred[warp] = e;
        __syncthreads();
        if (tid == 0) {
            float ss = 0.f;
            for (int i = 0; i < 8; i++) ss += wred[i];
            g_pM[blockIdx.x * B_ + b] = bm;
            g_pS[blockIdx.x * B_ + b] = ss;
        }
        __syncthreads();
    }
}

// ==================== fused exit decision + next-layer skip ================
__global__ void exit_skip_k(const float* __restrict__ x,
                            const float* __restrict__ ew, const float* __restrict__ eb,
                            const float* __restrict__ swn, const float* __restrict__ sbn,
                            int li, int haveNext) {
    int tid = threadIdx.x;
    int warp = tid >> 5, lane = tid & 31;
    __shared__ float conf[B_], eps[B_], sp[B_];
    const int doskip = d_do_skip;

    if (!doskip) {
        if (warp < B_) {
            float m = -1e30f;
            for (int i = lane; i < NPB; i += 32) m = fmaxf(m, g_pM[i * B_ + warp]);
#pragma unroll
            for (int o = 16; o > 0; o >>= 1) m = fmaxf(m, __shfl_xor_sync(0xffffffff, m, o));
            float s = 0.f;
            for (int i = lane; i < NPB; i += 32)
                s += g_pS[i * B_ + warp] * __expf(g_pM[i * B_ + warp] - m);
#pragma unroll
            for (int o = 16; o > 0; o >>= 1) s += __shfl_xor_sync(0xffffffff, s, o);
            if (lane == 0) conf[warp] = 1.f / s;
        } else {
            int b = warp - B_;
            const float* xr = x + ((ll)b * T_ + (T_ - 1)) * D_;
            float e = 0.f;
#pragma unroll 8
            for (int i = lane; i < D_; i += 32) e += xr[i] * ew[i];
#pragma unroll
            for (int o = 16; o > 0; o >>= 1) e += __shfl_xor_sync(0xffffffff, e, o);
            if (lane == 0) eps[b] = 1.f / (1.f + expf(-(e + eb[0])));
        }
    }
    __syncthreads();
    if (tid < B_) {
        int nw = 0;
        if (!doskip) {
            int should = (conf[tid] > 0.9f) || (eps[tid] > 0.9f);
            nw = (should && !d_exited[tid]) ? 1 : 0;
        }
        d_newly[tid] = nw;
        if (nw) { d_exited[tid] = 1; d_exl[tid] = li; }
    }
    __syncthreads();
    if (haveNext) {
        if (warp < B_) {
            const float* xr = x + ((ll)warp * T_ + (T_ - 1)) * D_;
            float s = 0.f;
#pragma unroll 8
            for (int i = lane; i < D_; i += 32) s += xr[i] * swn[i];
#pragma unroll
            for (int o = 16; o > 0; o >>= 1) s += __shfl_xor_sync(0xffffffff, s, o);
            if (lane == 0) sp[warp] = 1.f / (1.f + expf(-(s + sbn[0])));
        }
        __syncthreads();
        if (tid == 0) {
            float cnt = 0.f, s = 0.f;
            for (int b = 0; b < B_; b++) {
                float a = d_exited[b] ? 0.f : 1.f;
                cnt += a; s += sp[b] * a;
            }
            float mean = s / fmaxf(cnt, 1.f);
            d_do_skip = (cnt > 0.f && mean < 0.1f) ? 1 : 0;
        }
    } else if (tid == 0) {
        d_do_skip = 0;
    }
}

// =====================  fast cp.async GEMM on packed operands ==============
// aSel: 0 h, 1 ao, 2 f1, 3 ex. wSel: 0 qkv(z), 1 wo, 2 w1, 5 w3, 3 w2, 4 lm.
// accumulate: 0 store, 1 +=, 2 atomicAdd. epiMode 1: silu(f1)*acc -> f1 pack.
template <int IBLK, int STG>
__global__ __launch_bounds__(256, (IBLK == 4) ? 1 : 2) void gemm_ws_k(
    int aSel, int wSel, int li, float* __restrict__ C,
    int M, int N, int K, int ldbU, int ldc,
    int aColStride, ll sCo, int accumulate, int gateMode, int splitK, int epiMode) {
    if (gateMode == 1 && d_do_skip) return;
    if (gateMode == 2 && !d_newly[blockIdx.z]) return;
    constexpr int BM = IBLK * 32;
    constexpr int SPA = BM + 8;
    constexpr int SPB = 136;
    constexpr int KP = 16;
    constexpr int AS = KP * SPA, BS = KP * SPB;
    constexpr int STAGE = 2 * AS + 2 * BS;
    constexpr int ACHROW = BM / 4;
    constexpr int ACH = KP * ACHROW;
    constexpr int BCH = KP * 32;
    constexpr int TCH = 2 * ACH + 2 * BCH;

    extern __shared__ uint32_t sm[];
    const int z = blockIdx.z;

    const uint32_t* aHp = (aSel == 0) ? g_hpH : ((aSel == 1) ? g_aopH :
                          ((aSel == 2) ? g_f1pH : g_exH));
    const uint32_t* aLp = (aSel == 0) ? g_hpL : ((aSel == 1) ? g_aopL :
                          ((aSel == 2) ? g_f1pL : g_exL));
    const uint32_t *bHp, *bLp;
    {
        ll off;
        switch (wSel) {
        case 0:
            off = (ll)li * (D_/2) * D_;
            bHp = ((z == 0) ? g_wqH : ((z == 1) ? g_wkH : g_wvH)) + off;
            bLp = ((z == 0) ? g_wqL : ((z == 1) ? g_wkL : g_wvL)) + off;
            break;
        case 1:
            off = (ll)li * (D_/2) * D_;
            bHp = g_woH + off; bLp = g_woL + off; break;
        case 2:
            off = (ll)li * (D_/2) * F_;
            bHp = g_w1H + off; bLp = g_w1L + off; break;
        case 5:
            off = (ll)li * (D_/2) * F_;
            bHp = g_w3H + off; bLp = g_w3L + off; break;
        case 3:
            off = (ll)li * (F_/2) * D_;
            bHp = g_w2H + off; bLp = g_w2L + off; break;
        default:
            bHp = g_lmH; bLp = g_lmL; break;
        }
    }
    const int Ksub = K / splitK;
    const int kpBase = (splitK > 1) ? z * (Ksub / 2) : 0;
    const int aOff = (splitK > 1) ? 0 : z * aColStride;
    float* Cb = (splitK > 1) ? C : (C + (ll)z * sCo);

    const int tid = threadIdx.x;
    const int lane = tid & 31;
    const int warp = tid >> 5;
    const int warpRow = warp >> 2;
    const int warpCol = warp & 3;
    const int rowBase = blockIdx.y * BM;
    const int colBase = blockIdx.x * 128;
    const int lq = lane >> 2;
    const int lr = lane & 3;

    auto loadTile = [&](int t, int s) {
        uint32_t* st = sm + s * STAGE;
        int kp0 = kpBase + t * KP;
#pragma unroll
        for (int c = tid; c < TCH; c += 256) {
            uint32_t* dst; const uint32_t* src;
            if (c < 2 * ACH) {
                int cc = c; const uint32_t* g = aHp; uint32_t* ss = st;
                if (cc >= ACH) { cc -= ACH; g = aLp; ss = st + AS; }
                int row = cc / ACHROW, col = (cc % ACHROW) * 4;
                dst = ss + row * SPA + col;
                src = g + (ll)(kp0 + row) * MT + aOff + rowBase + col;
            } else {
                int cc = c - 2 * ACH; const uint32_t* g = bHp; uint32_t* ss = st + 2 * AS;
                if (cc >= BCH) { cc -= BCH; g = bLp; ss += BS; }
                int row = cc >> 5, col = (cc & 31) * 4;
                dst = ss + row * SPB + col;
                src = g + (ll)(kp0 + row) * ldbU + colBase + col;
            }
            uint32_t da = (uint32_t)__cvta_generic_to_shared(dst);
            asm volatile("cp.async.cg.shared.global [%0], [%1], 16;\n"
                         :: "r"(da), "l"(src));
        }
        asm volatile("cp.async.commit_group;\n");
    };

    float acc[IBLK][4][4];
#pragma unroll
    for (int i = 0; i < IBLK; i++)
#pragma unroll
        for (int j = 0; j < 4; j++)
#pragma unroll
            for (int r = 0; r < 4; r++) acc[i][j][r] = 0.f;

    const int nt = Ksub / 32;
#pragma unroll
    for (int s = 0; s < STG - 1; s++) loadTile(s, s);

    for (int t = 0; t < nt; t++) {
        asm volatile("cp.async.wait_group %0;\n" :: "n"(STG - 2));
        __syncthreads();
        int tn = t + STG - 1;
        if (tn < nt) loadTile(tn, tn % STG);
        else asm volatile("cp.async.commit_group;\n");

        const uint32_t* AsH = sm + (t % STG) * STAGE;
        const uint32_t* AsL = AsH + AS;
        const uint32_t* BsH = AsH + 2 * AS;
        const uint32_t* BsL = BsH + BS;
#pragma unroll
        for (int st2 = 0; st2 < 2; st2++) {
            int base = st2 * 8;
            uint32_t aH[IBLK][4], aL[IBLK][4], bH[4][2], bL[4][2];
#pragma unroll
            for (int i = 0; i < IBLK; i++) {
                int m0 = warpRow * (IBLK * 16) + i * 16 + lq;
                aH[i][0] = AsH[(base + lr) * SPA + m0];
                aH[i][1] = AsH[(base + lr) * SPA + m0 + 8];
                aH[i][2] = AsH[(base + lr + 4) * SPA + m0];
                aH[i][3] = AsH[(base + lr + 4) * SPA + m0 + 8];
                aL[i][0] = AsL[(base + lr) * SPA + m0];
                aL[i][1] = AsL[(base + lr) * SPA + m0 + 8];
                aL[i][2] = AsL[(base + lr + 4) * SPA + m0];
                aL[i][3] = AsL[(base + lr + 4) * SPA + m0 + 8];
            }
#pragma unroll
            for (int j = 0; j < 4; j++) {
                int n0 = warpCol * 32 + j * 8 + lq;
                bH[j][0] = BsH[(base + lr) * SPB + n0];
                bH[j][1] = BsH[(base + lr + 4) * SPB + n0];
                bL[j][0] = BsL[(base + lr) * SPB + n0];
                bL[j][1] = BsL[(base + lr + 4) * SPB + n0];
            }
#pragma unroll
            for (int i = 0; i < IBLK; i++)
#pragma unroll
                for (int j = 0; j < 4; j++) MMA_BF16(acc[i][j], aH[i], bL[j]);
#pragma unroll
            for (int i = 0; i < IBLK; i++)
#pragma unroll
                for (int j = 0; j < 4; j++) MMA_BF16(acc[i][j], aL[i], bH[j]);
#pragma unroll
            for (int i = 0; i < IBLK; i++)
#pragma unroll
                for (int j = 0; j < 4; j++) MMA_BF16(acc[i][j], aH[i], bH[j]);
        }
    }

#pragma unroll
    for (int i = 0; i < IBLK; i++) {
#pragma unroll
        for (int r2 = 0; r2 < 2; r2++) {
            int gm = rowBase + warpRow * (IBLK * 16) + i * 16 + lq + r2 * 8;
            if (gm >= M) continue;
            float* crow = Cb + (ll)gm * ldc;
            const float* f1row = g_f13 + (ll)gm * F_;
#pragma unroll
            for (int j = 0; j < 4; j++) {
                int gn = colBase + warpCol * 32 + j * 8 + lr * 2;
                float v0 = acc[i][j][r2 * 2 + 0];
                float v1 = acc[i][j][r2 * 2 + 1];
                if (epiMode == 1) {
                    float f10 = f1row[gn], f11 = f1row[gn + 1];
                    float o0 = (f10 / (1.f + expf(-f10))) * v0;
                    float o1 = (f11 / (1.f + expf(-f11))) * v1;
                    uint32_t hh, lo;
                    split_pack(o0, o1, hh, lo);
                    ll o = (ll)(gn >> 1) * MT + gm;
                    g_f1pH[o] = hh; g_f1pL[o] = lo;
                    continue;
                }
                if (gn < N) {
                    if (accumulate == 2)      atomicAdd(crow + gn, v0);
                    else if (accumulate == 1) crow[gn] += v0;
                    else                      crow[gn] = v0;
                }
                if (gn + 1 < N) {
                    if (accumulate == 2)      atomicAdd(crow + gn + 1, v1);
                    else if (accumulate == 1) crow[gn + 1] += v1;
                    else                      crow[gn + 1] = v1;
                }
            }
        }
    }
}

#define SMEM_WS2 (4 * (2*16*(64+8)  + 2*16*136) * 4)
#define SMEM_WS4 (4 * (2*16*(128+8) + 2*16*136) * 4)

static void gemm_fast(int aSel, int wSel, int li, float* C,
                      int M, int N, int K, int ldbU, int ldc,
                      int batch, int aColStride, ll sCo, int acc, int gate,
                      int epiMode = 0) {
    int nx = N / 128;
    int b128 = nx * (M / 128) * batch;
    if (b128 >= 296) {
        dim3 g(nx, M / 128, batch);
        gemm_ws_k<4, 4><<<g, 256, SMEM_WS4>>>(aSel, wSel, li, C, M, N, K, ldbU, ldc,
                                              aColStride, sCo, acc, gate, 1, epiMode);
    } else {
        dim3 g(nx, M / 64, batch);
        gemm_ws_k<2, 4><<<g, 256, SMEM_WS2>>>(aSel, wSel, li, C, M, N, K, ldbU, ldc,
                                              aColStride, sCo, acc, gate, 1, epiMode);
    }
}

static void gemm_fast_sk(int aSel, int wSel, int li, float* C,
                         int M, int N, int K, int ldbU, int ldc,
                         int splitK, int gate) {
    dim3 g(N / 128, M / 64, splitK);
    gemm_ws_k<2, 4><<<g, 256, SMEM_WS2>>>(aSel, wSel, li, C, M, N, K, ldbU, ldc,
                                          0, 0, 2, gate, splitK, 0);
}

// ---------------------------------------------------------------------------
extern "C" void kernel_launch(void* const* d_in, const int* in_sizes, int n_in,
                              void* d_out, int out_size) {
    const int*   ids        = (const int*)  d_in[0];
    const float* embed      = (const float*)d_in[1];
    const float* wq         = (const float*)d_in[2];
    const float* wk         = (const float*)d_in[3];
    const float* wv         = (const float*)d_in[4];
    const float* wo         = (const float*)d_in[5];
    const float* w1         = (const float*)d_in[6];
    const float* w2         = (const float*)d_in[7];
    const float* w3         = (const float*)d_in[8];
    const float* norm1      = (const float*)d_in[9];
    const float* norm2      = (const float*)d_in[10];
    const float* final_norm = (const float*)d_in[11];
    const float* lm_head    = (const float*)d_in[12];
    const float* exit_w     = (const float*)d_in[13];
    const float* exit_b     = (const float*)d_in[14];
    const float* skip_w     = (const float*)d_in[15];
    const float* skip_b     = (const float*)d_in[16];
    float* out = (float*)d_out;

    cudaFuncSetAttribute(gemm_ws_k<2, 4>, cudaFuncAttributeMaxDynamicSharedMemorySize, SMEM_WS2);
    cudaFuncSetAttribute(gemm_ws_k<4, 4>, cudaFuncAttributeMaxDynamicSharedMemorySize, SMEM_WS4);
    cudaFuncSetAttribute(flash_k, cudaFuncAttributeMaxDynamicSharedMemorySize, FLASH_SMEM);

    float *px, *pqkv, *pf13;
    cudaGetSymbolAddress((void**)&px,   g_x);
    cudaGetSymbolAddress((void**)&pqkv, g_qkv);
    cudaGetSymbolAddress((void**)&pf13, g_f13);

    init_k<<<1, 32>>>();
    prepack_k<<<(int)((TOTPAIRS + 255) / 256), 256>>>(wq, wk, wv, wo, w1, w2, w3, lm_head);
    rope_tables_k<<<(T_ * (HD_ / 2)) / 256, 256>>>();
    embed_k<<<(B_ * T_ * D_) / 256, 256>>>(ids, embed);

    for (int li = 0; li < L_; li++) {
        // transformer block (gated by do_skip, set by previous layer's exit_skip_k)
        rmsnorm_k<<<B_ * T_, 256>>>(px, norm1 + (ll)li * D_, nullptr, D_, D_, 1, 1, 1);
        gemm_fast(0, 0, li, pqkv, MT, D_, D_, D_, D_, 3, 0, (ll)BTD, 0, 1);
        flash_k<<<dim3(2, B_ * H_), 256, FLASH_SMEM>>>();   // rope fused inside
        gemm_fast_sk(1, 1, li, px, MT, D_, D_, D_, D_, 2, 1);
        rmsnorm_k<<<B_ * T_, 256>>>(px, norm2 + (ll)li * D_, nullptr, D_, D_, 1, 1, 1);
        // f1 = h @ w1 (fp32), then w3 GEMM with silu-pack epilogue
        gemm_fast(0, 2, li, pf13, MT, F_, D_, F_, F_, 1, 0, 0, 0, 1, 0);
        gemm_fast(0, 5, li, pf13, MT, F_, D_, F_, F_, 1, 0, 0, 0, 1, 1);
        gemm_fast_sk(2, 3, li, px, MT, D_, F_, D_, D_, 2, 1);

        // exit logic + next-layer skip (fused; hlast rmsnorm inline)
        logits_exit_k<<<NPB, 256>>>(px, final_norm);
        int nli = (li + 1 < L_) ? (li + 1) : (L_ - 1);
        exit_skip_k<<<1, 256>>>(px, exit_w + (ll)li * D_, exit_b + li,
                                skip_w + (ll)nli * D_, skip_b + nli,
                                li, li + 1 < L_ ? 1 : 0);

        // snapshot rmsnorm(x, final_norm) for newly-exited batches -> g_ex
        rmsnorm_k<<<B_ * T_, 256>>>(px, final_norm, nullptr, D_, D_, 2, T_, 3);
    }

    // final: snapshot for never-exited, then ONE logits GEMM for all batches
    finalize_k<<<1, 32>>>();
    rmsnorm_k<<<B_ * T_, 256>>>(px, final_norm, nullptr, D_, D_, 2, T_, 3);
    gemm_fast(3, 4, 0, out, T_, V_, D_, V_, V_, B_, T_, (ll)T_ * V_, 0, 0);

    if (out_size >= B_ * T_ * V_ + B_)
        write_exl_k<<<1, 32>>>(out + (ll)B_ * T_ * V_);
}